// round 7
// baseline (speedup 1.0000x reference)
#include <cuda_runtime.h>

#define BB 2
#define CC 512
#define HH 256
#define WW 256
#define EPSV 1e-5f
#define NCTA 512            // persistent grid; 4 CTAs/SM guaranteed via launch_bounds

// ---------------- scratch (device globals; no allocations allowed) ----------
__device__ float g_y1[BB * CC * WW];     // [b][c][w]
__device__ float g_y2[BB * CC * HH];     // [b][c][h]
__device__ float g_dot[CC * BB];         // flat [c][b]; linear view == num[b][k]
__device__ float g_h[BB * 2 * CC];       // [b][1024]
__device__ float g_logits[BB * CC];      // [b][c]

__device__ unsigned g_cnt[4];            // grid-barrier arrival counters
__device__ unsigned g_gen[4];            // grid-barrier generations (monotone)

__device__ __forceinline__ float4 ldcg4(const float4* p) { return __ldcg(p); }
__device__ __forceinline__ void prefetchL2(const void* p) {
    asm volatile("prefetch.global.L2 [%0];" :: "l"(p));
}
__device__ __forceinline__ float hsum4(float4 a) { return (a.x + a.y) + (a.z + a.w); }
__device__ __forceinline__ float dotp4(float4 a, float4 b) {
    return a.x * b.x + a.y * b.y + a.z * b.z + a.w * b.w;
}
__device__ __forceinline__ float4 relu4(float4 a, float r, float c) {
    float4 o;
    o.x = fmaxf(0.f, fmaf(a.x, r, c));
    o.y = fmaxf(0.f, fmaf(a.y, r, c));
    o.z = fmaxf(0.f, fmaf(a.z, r, c));
    o.w = fmaxf(0.f, fmaf(a.w, r, c));
    return o;
}

// software grid barrier: all NCTA CTAs co-resident.
__device__ __forceinline__ void gridbar(int i) {
    __syncthreads();
    if (threadIdx.x == 0) {
        __threadfence();
        volatile unsigned* genp = (volatile unsigned*)&g_gen[i];
        unsigned gen = *genp;                          // read BEFORE arriving
        unsigned arrived = atomicAdd(&g_cnt[i], 1u);
        if (arrived == NCTA - 1) {
            atomicExch(&g_cnt[i], 0u);                 // reset for next replay
            __threadfence();
            atomicAdd(&g_gen[i], 1u);                  // release
        } else {
            while (*genp == gen) { __nanosleep(32); }
        }
        __threadfence();
    }
    __syncthreads();
}

// block-wide reductions over 256 threads (helpers; all threads must call)
__device__ __forceinline__ float blockMax256(float v, float* sh) {
    #pragma unroll
    for (int off = 16; off; off >>= 1) v = fmaxf(v, __shfl_xor_sync(0xffffffffu, v, off));
    int lane = threadIdx.x & 31, w = threadIdx.x >> 5;
    if (lane == 0) sh[w] = v;
    __syncthreads();
    if (threadIdx.x == 0) {
        float m = sh[0];
        #pragma unroll
        for (int i = 1; i < 8; ++i) m = fmaxf(m, sh[i]);
        sh[0] = m;
    }
    __syncthreads();
    float r = sh[0];
    __syncthreads();
    return r;
}
__device__ __forceinline__ float blockSum256(float v, float* sh) {
    #pragma unroll
    for (int off = 16; off; off >>= 1) v += __shfl_xor_sync(0xffffffffu, v, off);
    int lane = threadIdx.x & 31, w = threadIdx.x >> 5;
    if (lane == 0) sh[w] = v;
    __syncthreads();
    if (threadIdx.x == 0) {
        float s = sh[0];
        #pragma unroll
        for (int i = 1; i < 8; ++i) s += sh[i];
        sh[0] = s;
    }
    __syncthreads();
    float r = sh[0];
    __syncthreads();
    return r;
}

// ============================================================================
// One persistent kernel. Phases:
//   P1: dwconv reductions (each CTA: planes i, i+512; warp-per-row scheme)
//   A : BN stats + ReLU + dot (warp per channel)
//   B : linear1 (warp per output row, K=512)
//   C : linear2 (warp per output row, K=1024)
//   D : per-CTA redundant softmax (no barrier after; local values only)
//   P4: out = x * scale (planes i+512 then i -> L2-warm tail first)
// ============================================================================
__global__ __launch_bounds__(256, 4)
void kfused(const float* __restrict__ x, float* __restrict__ out,
            const float* __restrict__ w1, const float* __restrict__ w2,
            const float* __restrict__ g1, const float* __restrict__ b1,
            const float* __restrict__ g2, const float* __restrict__ b2,
            const float* __restrict__ lw1, const float* __restrict__ lb1,
            const float* __restrict__ lw2, const float* __restrict__ lb2) {
    __shared__ float  w1s[HH];
    __shared__ float  w2s[WW];
    __shared__ float4 y1p[8][64];        // per-warp y1 partials
    __shared__ float  sred[8];

    int t    = threadIdx.x;
    int lane = t & 31;
    int wrp  = t >> 5;

    // ---------------- P1: depthwise reductions, 2 planes per CTA ------------
    #pragma unroll 1
    for (int pp = 0; pp < 2; ++pp) {
        int bc = blockIdx.x + pp * NCTA;             // plane i, then i+512
        int c  = bc & (CC - 1);
        const float4* plane = reinterpret_cast<const float4*>(x) + (size_t)bc * (HH * WW / 4);

        w1s[t] = w1[c * HH + t];
        w2s[t] = w2[c * WW + t];
        __syncthreads();

        float4 w2a = reinterpret_cast<const float4*>(w2s)[lane];
        float4 w2b = reinterpret_cast<const float4*>(w2s)[lane + 32];
        float4 acc1a = make_float4(0.f, 0.f, 0.f, 0.f);
        float4 acc1b = make_float4(0.f, 0.f, 0.f, 0.f);
        float  y2v = 0.f;

        // warp wrp owns rows wrp, wrp+8, ..., wrp+248; one full 1KB row / step
        #pragma unroll 4
        for (int k = 0; k < 32; ++k) {
            int row = wrp + 8 * k;
            float4 v0 = plane[row * 64 + lane];
            float4 v1 = plane[row * 64 + lane + 32];
            float  wv = w1s[row];
            acc1a.x = fmaf(v0.x, wv, acc1a.x);
            acc1a.y = fmaf(v0.y, wv, acc1a.y);
            acc1a.z = fmaf(v0.z, wv, acc1a.z);
            acc1a.w = fmaf(v0.w, wv, acc1a.w);
            acc1b.x = fmaf(v1.x, wv, acc1b.x);
            acc1b.y = fmaf(v1.y, wv, acc1b.y);
            acc1b.z = fmaf(v1.z, wv, acc1b.z);
            acc1b.w = fmaf(v1.w, wv, acc1b.w);
            float p = dotp4(v0, w2a) + dotp4(v1, w2b);
            #pragma unroll
            for (int off = 16; off; off >>= 1)
                p += __shfl_xor_sync(0xffffffffu, p, off);
            if (lane == k) y2v = p;                  // lane k banks row wrp+8k
        }

        g_y2[bc * HH + wrp + 8 * lane] = y2v;
        y1p[wrp][lane]      = acc1a;
        y1p[wrp][lane + 32] = acc1b;
        __syncthreads();

        if (t < 64) {
            float4 s = y1p[0][t];
            #pragma unroll
            for (int i = 1; i < 8; ++i) {
                float4 a = y1p[i][t];
                s.x += a.x; s.y += a.y; s.z += a.z; s.w += a.w;
            }
            reinterpret_cast<float4*>(g_y1 + (size_t)bc * WW)[t] = s;
        }
        __syncthreads();                             // protect smem reuse
    }

    // prefetch MLP weights into L2 AFTER the big stream (so they survive)
    {
        int gt = blockIdx.x * 256 + t;               // 0..131071
        if (gt < 16384)          prefetchL2((const char*)lw1 + (size_t)gt * 128);
        else if (gt < 32768)     prefetchL2((const char*)lw2 + (size_t)(gt - 16384) * 128);
    }

    gridbar(0);

    int gw = blockIdx.x * 8 + wrp;                   // global warp id 0..4095

    // ---------------- A: BN stats + ReLU + dot (warp per channel) -----------
    if (gw < CC) {
        int c = gw;
        const float4* p10 = reinterpret_cast<const float4*>(g_y1 + c * WW);
        const float4* p11 = reinterpret_cast<const float4*>(g_y1 + CC * WW + c * WW);
        const float4* p20 = reinterpret_cast<const float4*>(g_y2 + c * HH);
        const float4* p21 = reinterpret_cast<const float4*>(g_y2 + CC * HH + c * HH);

        float4 a10a = ldcg4(p10 + lane), a10b = ldcg4(p10 + lane + 32);
        float4 a11a = ldcg4(p11 + lane), a11b = ldcg4(p11 + lane + 32);
        float4 a20a = ldcg4(p20 + lane), a20b = ldcg4(p20 + lane + 32);
        float4 a21a = ldcg4(p21 + lane), a21b = ldcg4(p21 + lane + 32);

        float s1 = hsum4(a10a) + hsum4(a10b) + hsum4(a11a) + hsum4(a11b);
        float q1 = dotp4(a10a, a10a) + dotp4(a10b, a10b) + dotp4(a11a, a11a) + dotp4(a11b, a11b);
        float s2 = hsum4(a20a) + hsum4(a20b) + hsum4(a21a) + hsum4(a21b);
        float q2 = dotp4(a20a, a20a) + dotp4(a20b, a20b) + dotp4(a21a, a21a) + dotp4(a21b, a21b);

        #pragma unroll
        for (int off = 16; off; off >>= 1) {
            s1 += __shfl_xor_sync(0xffffffffu, s1, off);
            q1 += __shfl_xor_sync(0xffffffffu, q1, off);
            s2 += __shfl_xor_sync(0xffffffffu, s2, off);
            q2 += __shfl_xor_sync(0xffffffffu, q2, off);
        }

        const float invn = 1.f / (float)(BB * WW);
        float m1 = s1 * invn, v1 = q1 * invn - m1 * m1;
        float m2 = s2 * invn, v2 = q2 * invn - m2 * m2;
        float r1 = rsqrtf(v1 + EPSV) * g1[c];
        float c1 = b1[c] - m1 * r1;
        float r2 = rsqrtf(v2 + EPSV) * g2[c];
        float c2 = b2[c] - m2 * r2;

        float d0 = dotp4(relu4(a10a, r1, c1), relu4(a20a, r2, c2))
                 + dotp4(relu4(a10b, r1, c1), relu4(a20b, r2, c2));
        float d1 = dotp4(relu4(a11a, r1, c1), relu4(a21a, r2, c2))
                 + dotp4(relu4(a11b, r1, c1), relu4(a21b, r2, c2));
        #pragma unroll
        for (int off = 16; off; off >>= 1) {
            d0 += __shfl_xor_sync(0xffffffffu, d0, off);
            d1 += __shfl_xor_sync(0xffffffffu, d1, off);
        }
        if (lane == 0) {
            g_dot[c * BB + 0] = d0;
            g_dot[c * BB + 1] = d1;
        }
    }

    gridbar(1);

    // ---------------- B: linear1, warp per output row (K=512) ---------------
    if (gw < 2 * CC) {
        int j = gw;
        const float4* wr = reinterpret_cast<const float4*>(lw1 + (size_t)j * CC);
        const float4* i0 = reinterpret_cast<const float4*>(g_dot);
        const float4* i1 = reinterpret_cast<const float4*>(g_dot + CC);
        float a0 = 0.f, a1 = 0.f;
        #pragma unroll
        for (int i = 0; i < 4; ++i) {
            float4 wq = __ldg(wr + lane + 32 * i);
            float4 v0 = ldcg4(i0 + lane + 32 * i);
            float4 v1 = ldcg4(i1 + lane + 32 * i);
            a0 += dotp4(wq, v0);
            a1 += dotp4(wq, v1);
        }
        #pragma unroll
        for (int off = 16; off; off >>= 1) {
            a0 += __shfl_xor_sync(0xffffffffu, a0, off);
            a1 += __shfl_xor_sync(0xffffffffu, a1, off);
        }
        if (lane == 0) {
            float bj = lb1[j];
            g_h[j]          = a0 + bj;
            g_h[2 * CC + j] = a1 + bj;
        }
    }

    gridbar(2);

    // ---------------- C: linear2, warp per output row (K=1024) --------------
    if (gw < CC) {
        int j = gw;
        const float4* wr = reinterpret_cast<const float4*>(lw2 + (size_t)j * 2 * CC);
        const float4* i0 = reinterpret_cast<const float4*>(g_h);
        const float4* i1 = reinterpret_cast<const float4*>(g_h + 2 * CC);
        float a0 = 0.f, a1 = 0.f;
        #pragma unroll
        for (int i = 0; i < 8; ++i) {
            float4 wq = __ldg(wr + lane + 32 * i);
            float4 v0 = ldcg4(i0 + lane + 32 * i);
            float4 v1 = ldcg4(i1 + lane + 32 * i);
            a0 += dotp4(wq, v0);
            a1 += dotp4(wq, v1);
        }
        #pragma unroll
        for (int off = 16; off; off >>= 1) {
            a0 += __shfl_xor_sync(0xffffffffu, a0, off);
            a1 += __shfl_xor_sync(0xffffffffu, a1, off);
        }
        if (lane == 0) {
            float bj = lb2[j];
            g_logits[j]      = a0 + bj;
            g_logits[CC + j] = a1 + bj;
        }
    }

    gridbar(3);

    // ---------------- D: per-CTA softmax (redundant, local result) ----------
    float l0a = __ldcg(&g_logits[t]);
    float l0b = __ldcg(&g_logits[256 + t]);
    float l1a = __ldcg(&g_logits[CC + t]);
    float l1b = __ldcg(&g_logits[CC + 256 + t]);

    float M0 = blockMax256(fmaxf(l0a, l0b), sred);
    float M1 = blockMax256(fmaxf(l1a, l1b), sred);
    float S0 = blockSum256(expf(l0a - M0) + expf(l0b - M0), sred);
    float S1 = blockSum256(expf(l1a - M1) + expf(l1b - M1), sred);

    int ci = blockIdx.x;                               // channel of this CTA's planes
    float sc0 = expf(__ldcg(&g_logits[ci])      - M0) / S0;   // b=0, plane ci
    float sc1 = expf(__ldcg(&g_logits[CC + ci]) - M1) / S1;   // b=1, plane 512+ci

    // ---------------- P4: scale; L2-warm second-half planes first -----------
    #pragma unroll 1
    for (int pp = 0; pp < 2; ++pp) {
        int   bc = pp ? blockIdx.x : (NCTA + blockIdx.x);
        float s  = pp ? sc0 : sc1;
        const float4* xp = reinterpret_cast<const float4*>(x)   + (size_t)bc * (HH * WW / 4);
        float4*       op = reinterpret_cast<float4*>(out)       + (size_t)bc * (HH * WW / 4);
        #pragma unroll 8
        for (int i = t; i < HH * WW / 4; i += 256) {
            float4 v = xp[i];
            v.x *= s; v.y *= s; v.z *= s; v.w *= s;
            __stcs(&op[i], v);
        }
    }
}

// ============================================================================
extern "C" void kernel_launch(void* const* d_in, const int* in_sizes, int n_in,
                              void* d_out, int out_size) {
    const float* x   = (const float*)d_in[0];
    const float* w1  = (const float*)d_in[1];
    const float* w2  = (const float*)d_in[2];
    const float* g1  = (const float*)d_in[3];
    const float* b1  = (const float*)d_in[4];
    const float* g2  = (const float*)d_in[5];
    const float* b2  = (const float*)d_in[6];
    const float* lw1 = (const float*)d_in[7];
    const float* lb1 = (const float*)d_in[8];
    const float* lw2 = (const float*)d_in[9];
    const float* lb2 = (const float*)d_in[10];
    float* out = (float*)d_out;

    kfused<<<NCTA, 256>>>(x, out, w1, w2, g1, b1, g2, b2, lw1, lb1, lw2, lb2);
}

// round 9
// speedup vs baseline: 1.0112x; 1.0112x over previous
#include <cuda_runtime.h>

#define BB 2
#define CC 512
#define HH 256
#define WW 256
#define EPSV 1e-5f
#define NCTA 148            // persistent-kernel grid for kmid

// ---------------- scratch (device globals; no allocations allowed) ----------
__device__ float g_y1[BB * CC * WW];     // [b][c][w]
__device__ float g_y2[BB * CC * HH];     // [b][c][h]
__device__ float g_dot[CC * BB];         // flat [c][b]; linear view == num[b][k]
__device__ float g_h[BB * 2 * CC];       // [b][1024]
__device__ float g_logits[BB * CC];      // [b][c]
__device__ float g_scale[BB * CC];       // [b][c]

__device__ unsigned g_cnt[3];            // grid-barrier arrival counters
__device__ unsigned g_gen[3];            // grid-barrier generations (monotone)

__device__ __forceinline__ float4 ldcg4(const float4* p) { return __ldcg(p); }
__device__ __forceinline__ void prefetchL2(const void* p) {
    asm volatile("prefetch.global.L2 [%0];" :: "l"(p));
}
__device__ __forceinline__ float hsum4(float4 a) { return (a.x + a.y) + (a.z + a.w); }
__device__ __forceinline__ float dotp4(float4 a, float4 b) {
    return a.x * b.x + a.y * b.y + a.z * b.z + a.w * b.w;
}
__device__ __forceinline__ float4 relu4(float4 a, float r, float c) {
    float4 o;
    o.x = fmaxf(0.f, fmaf(a.x, r, c));
    o.y = fmaxf(0.f, fmaf(a.y, r, c));
    o.z = fmaxf(0.f, fmaf(a.z, r, c));
    o.w = fmaxf(0.f, fmaf(a.w, r, c));
    return o;
}

// ============================================================================
// k1: per-(b,c) plane: y1[w] = sum_h x[h][w]*w1[h], y2[h] = sum_w x[h][w]*w2[w]
// Single pass over x (268 MB), DEFAULT (allocating) loads: the tail of this
// stream stays in L2 for k4, which walks planes in REVERSE order.
// grid = B*C = 1024, block = 256.
// ============================================================================
__global__ __launch_bounds__(256) void k1(const float* __restrict__ x,
                                          const float* __restrict__ w1,
                                          const float* __restrict__ w2) {
    int bc = blockIdx.x;                 // b*CC + c
    int c  = bc & (CC - 1);
    const float4* plane = reinterpret_cast<const float4*>(x) + (size_t)bc * (HH * WW / 4);

    __shared__ float  w1s[HH];
    __shared__ float  w2s[WW];
    __shared__ float  y2part[HH][2];
    __shared__ float4 acc1s[256];

    int t = threadIdx.x;
    w1s[t] = w1[c * HH + t];
    w2s[t] = w2[c * WW + t];
    __syncthreads();

    int r    = t >> 6;
    int q    = t & 63;
    int lane = t & 31;
    int par  = (t >> 5) & 1;

    float4 w2q  = reinterpret_cast<const float4*>(w2s)[q];
    float4 acc1 = make_float4(0.f, 0.f, 0.f, 0.f);
    float  y2acc[2];

    #pragma unroll
    for (int half = 0; half < 2; ++half) {
        float acc = 0.f;
        #pragma unroll 8
        for (int ii = 0; ii < 32; ++ii) {
            int i   = half * 32 + ii;
            int row = 4 * i + r;
            float4 v   = plane[row * (WW / 4) + q];
            float  w1v = w1s[row];
            acc1.x = fmaf(v.x, w1v, acc1.x);
            acc1.y = fmaf(v.y, w1v, acc1.y);
            acc1.z = fmaf(v.z, w1v, acc1.z);
            acc1.w = fmaf(v.w, w1v, acc1.w);
            float p = v.x * w2q.x + v.y * w2q.y + v.z * w2q.z + v.w * w2q.w;
            #pragma unroll
            for (int off = 16; off; off >>= 1)
                p += __shfl_xor_sync(0xffffffffu, p, off);
            if (lane == ii) acc += p;
        }
        y2acc[half] = acc;
    }

    y2part[4 * lane        + r][par] = y2acc[0];
    y2part[4 * (32 + lane) + r][par] = y2acc[1];
    acc1s[t] = acc1;
    __syncthreads();

    g_y2[bc * HH + t] = y2part[t][0] + y2part[t][1];

    if (t < 64) {
        float4 a0 = acc1s[t], a1 = acc1s[64 + t], a2 = acc1s[128 + t], a3 = acc1s[192 + t];
        float4 o;
        o.x = (a0.x + a1.x) + (a2.x + a3.x);
        o.y = (a0.y + a1.y) + (a2.y + a3.y);
        o.z = (a0.z + a1.z) + (a2.z + a3.z);
        o.w = (a0.w + a1.w) + (a2.w + a3.w);
        reinterpret_cast<float4*>(g_y1 + (size_t)bc * WW)[t] = o;
    }
}

// ============================================================================
// software grid barrier: all NCTA CTAs co-resident (NCTA <= #SMs).
// ============================================================================
__device__ __forceinline__ void gridbar(int i) {
    __syncthreads();
    if (threadIdx.x == 0) {
        __threadfence();
        volatile unsigned* genp = (volatile unsigned*)&g_gen[i];
        unsigned gen = *genp;                          // read BEFORE arriving
        unsigned arrived = atomicAdd(&g_cnt[i], 1u);
        if (arrived == NCTA - 1) {
            atomicExch(&g_cnt[i], 0u);                 // reset for next replay
            __threadfence();
            atomicAdd(&g_gen[i], 1u);                  // release
        } else {
            while (*genp == gen) { __nanosleep(32); }
        }
        __threadfence();
    }
    __syncthreads();
}

// ============================================================================
// kmid: fused BN+ReLU+dot -> linear1 -> linear2 -> softmax.
// Persistent, grid = NCTA, block = 256. MLP weights prefetched into L2.
// ============================================================================
__global__ __launch_bounds__(256) void kmid(const float* __restrict__ g1, const float* __restrict__ b1,
                                            const float* __restrict__ g2, const float* __restrict__ b2,
                                            const float* __restrict__ lw1, const float* __restrict__ lb1,
                                            const float* __restrict__ lw2, const float* __restrict__ lb2) {
    int t    = threadIdx.x;
    int lane = t & 31;
    int wrp  = t >> 5;
    int gw   = blockIdx.x * 8 + wrp;

    // ---- prefetch MLP weights into L2 (1 line per thread) ----
    {
        int gt = blockIdx.x * 256 + t;
        if (gt < 16384)          prefetchL2((const char*)lw1 + (size_t)gt * 128);
        else if (gt < 32768)     prefetchL2((const char*)lw2 + (size_t)(gt - 16384) * 128);
    }

    // ---- phase A: per-channel BN stats + ReLU + dot (one warp per channel) --
    if (gw < CC) {
        int c = gw;
        const float4* p10 = reinterpret_cast<const float4*>(g_y1 + c * WW);
        const float4* p11 = reinterpret_cast<const float4*>(g_y1 + CC * WW + c * WW);
        const float4* p20 = reinterpret_cast<const float4*>(g_y2 + c * HH);
        const float4* p21 = reinterpret_cast<const float4*>(g_y2 + CC * HH + c * HH);

        float4 a10a = ldcg4(p10 + lane), a10b = ldcg4(p10 + lane + 32);
        float4 a11a = ldcg4(p11 + lane), a11b = ldcg4(p11 + lane + 32);
        float4 a20a = ldcg4(p20 + lane), a20b = ldcg4(p20 + lane + 32);
        float4 a21a = ldcg4(p21 + lane), a21b = ldcg4(p21 + lane + 32);

        float s1 = hsum4(a10a) + hsum4(a10b) + hsum4(a11a) + hsum4(a11b);
        float q1 = dotp4(a10a, a10a) + dotp4(a10b, a10b) + dotp4(a11a, a11a) + dotp4(a11b, a11b);
        float s2 = hsum4(a20a) + hsum4(a20b) + hsum4(a21a) + hsum4(a21b);
        float q2 = dotp4(a20a, a20a) + dotp4(a20b, a20b) + dotp4(a21a, a21a) + dotp4(a21b, a21b);

        #pragma unroll
        for (int off = 16; off; off >>= 1) {
            s1 += __shfl_xor_sync(0xffffffffu, s1, off);
            q1 += __shfl_xor_sync(0xffffffffu, q1, off);
            s2 += __shfl_xor_sync(0xffffffffu, s2, off);
            q2 += __shfl_xor_sync(0xffffffffu, q2, off);
        }

        const float invn = 1.f / (float)(BB * WW);
        float m1 = s1 * invn, v1 = q1 * invn - m1 * m1;
        float m2 = s2 * invn, v2 = q2 * invn - m2 * m2;
        float r1 = rsqrtf(v1 + EPSV) * g1[c];
        float c1 = b1[c] - m1 * r1;
        float r2 = rsqrtf(v2 + EPSV) * g2[c];
        float c2 = b2[c] - m2 * r2;

        float d0 = dotp4(relu4(a10a, r1, c1), relu4(a20a, r2, c2))
                 + dotp4(relu4(a10b, r1, c1), relu4(a20b, r2, c2));
        float d1 = dotp4(relu4(a11a, r1, c1), relu4(a21a, r2, c2))
                 + dotp4(relu4(a11b, r1, c1), relu4(a21b, r2, c2));
        #pragma unroll
        for (int off = 16; off; off >>= 1) {
            d0 += __shfl_xor_sync(0xffffffffu, d0, off);
            d1 += __shfl_xor_sync(0xffffffffu, d1, off);
        }
        if (lane == 0) {
            g_dot[c * BB + 0] = d0;
            g_dot[c * BB + 1] = d1;
        }
    }

    gridbar(0);

    // ---- phase B: layer1, one warp per output row j (K=512) ----
    if (gw < 2 * CC) {
        int j = gw;
        const float4* wr = reinterpret_cast<const float4*>(lw1 + (size_t)j * CC);
        const float4* i0 = reinterpret_cast<const float4*>(g_dot);
        const float4* i1 = reinterpret_cast<const float4*>(g_dot + CC);
        float a0 = 0.f, a1 = 0.f;
        #pragma unroll
        for (int i = 0; i < 4; ++i) {
            float4 wq = __ldg(wr + lane + 32 * i);
            float4 v0 = ldcg4(i0 + lane + 32 * i);
            float4 v1 = ldcg4(i1 + lane + 32 * i);
            a0 += dotp4(wq, v0);
            a1 += dotp4(wq, v1);
        }
        #pragma unroll
        for (int off = 16; off; off >>= 1) {
            a0 += __shfl_xor_sync(0xffffffffu, a0, off);
            a1 += __shfl_xor_sync(0xffffffffu, a1, off);
        }
        if (lane == 0) {
            float bj = lb1[j];
            g_h[j]          = a0 + bj;
            g_h[2 * CC + j] = a1 + bj;
        }
    }

    gridbar(1);

    // ---- phase C: layer2, one warp per output row j (K=1024) ----
    if (gw < CC) {
        int j = gw;
        const float4* wr = reinterpret_cast<const float4*>(lw2 + (size_t)j * 2 * CC);
        const float4* i0 = reinterpret_cast<const float4*>(g_h);
        const float4* i1 = reinterpret_cast<const float4*>(g_h + 2 * CC);
        float a0 = 0.f, a1 = 0.f;
        #pragma unroll
        for (int i = 0; i < 8; ++i) {
            float4 wq = __ldg(wr + lane + 32 * i);
            float4 v0 = ldcg4(i0 + lane + 32 * i);
            float4 v1 = ldcg4(i1 + lane + 32 * i);
            a0 += dotp4(wq, v0);
            a1 += dotp4(wq, v1);
        }
        #pragma unroll
        for (int off = 16; off; off >>= 1) {
            a0 += __shfl_xor_sync(0xffffffffu, a0, off);
            a1 += __shfl_xor_sync(0xffffffffu, a1, off);
        }
        if (lane == 0) {
            float bj = lb2[j];
            g_logits[j]      = a0 + bj;
            g_logits[CC + j] = a1 + bj;
        }
    }

    gridbar(2);

    // ---- phase D: softmax over c per batch; CTA 0 only ----
    if (blockIdx.x == 0) {
        __shared__ float sh[8];
        #pragma unroll
        for (int b = 0; b < BB; ++b) {
            float v0 = __ldcg(&g_logits[b * CC + t]);
            float v1 = __ldcg(&g_logits[b * CC + 256 + t]);

            float m = fmaxf(v0, v1);
            #pragma unroll
            for (int off = 16; off; off >>= 1) m = fmaxf(m, __shfl_xor_sync(0xffffffffu, m, off));
            if (lane == 0) sh[wrp] = m;
            __syncthreads();
            if (t == 0) {
                float mm = sh[0];
                #pragma unroll
                for (int i = 1; i < 8; ++i) mm = fmaxf(mm, sh[i]);
                sh[0] = mm;
            }
            __syncthreads();
            m = sh[0];
            __syncthreads();

            float e0 = expf(v0 - m), e1 = expf(v1 - m);
            float s = e0 + e1;
            #pragma unroll
            for (int off = 16; off; off >>= 1) s += __shfl_xor_sync(0xffffffffu, s, off);
            if (lane == 0) sh[wrp] = s;
            __syncthreads();
            if (t == 0) {
                float ss = sh[0];
                #pragma unroll
                for (int i = 1; i < 8; ++i) ss += sh[i];
                sh[0] = ss;
            }
            __syncthreads();
            s = sh[0];
            __syncthreads();

            float inv = 1.f / s;
            g_scale[b * CC + t]       = e0 * inv;
            g_scale[b * CC + 256 + t] = e1 * inv;
        }
    }
}

// ============================================================================
// k4: out = x * scale[b,c]. REVERSED plane order: the first CTAs re-read the
// planes k1 streamed LAST (still L2-resident). Output stores are WRITE-THROUGH
// (__stwt, no L2 allocation) so the 268 MB output stream cannot evict x's tail.
// ============================================================================
__global__ __launch_bounds__(256) void k4(const float* __restrict__ x, float* __restrict__ out) {
    int idx  = (BB * CC * 8 - 1) - blockIdx.x;   // reversed schedule
    int bc   = idx >> 3;
    int part = idx & 7;
    float s = __ldcg(&g_scale[bc]);

    const float4* xp = reinterpret_cast<const float4*>(x)   + (size_t)bc * (HH * WW / 4) + part * 2048;
    float4*       op = reinterpret_cast<float4*>(out)       + (size_t)bc * (HH * WW / 4) + part * 2048;

    int t = threadIdx.x;
    #pragma unroll
    for (int i = 0; i < 8; ++i) {
        float4 v = ldcg4(&xp[i * 256 + t]);
        v.x *= s; v.y *= s; v.z *= s; v.w *= s;
        __stwt(&op[i * 256 + t], v);
    }
}

// ============================================================================
extern "C" void kernel_launch(void* const* d_in, const int* in_sizes, int n_in,
                              void* d_out, int out_size) {
    const float* x   = (const float*)d_in[0];
    const float* w1  = (const float*)d_in[1];
    const float* w2  = (const float*)d_in[2];
    const float* g1  = (const float*)d_in[3];
    const float* b1  = (const float*)d_in[4];
    const float* g2  = (const float*)d_in[5];
    const float* b2  = (const float*)d_in[6];
    const float* lw1 = (const float*)d_in[7];
    const float* lb1 = (const float*)d_in[8];
    const float* lw2 = (const float*)d_in[9];
    const float* lb2 = (const float*)d_in[10];
    float* out = (float*)d_out;

    k1<<<BB * CC, 256>>>(x, w1, w2);
    kmid<<<NCTA, 256>>>(g1, b1, g2, b2, lw1, lb1, lw2, lb2);
    k4<<<BB * CC * 8, 256>>>(x, out);
}